// round 10
// baseline (speedup 1.0000x reference)
// HRALinear on GB300 (compute_103 non-'a' toolchain => NO tcgen05/TMA).
// Compact-WY Householder prep + Ampere-style tf32 mma.sync GEMM.
//
// R9: K-permute REVERTED (it caused 2-way LDS.64 bank conflicts; crossbar
// phases, not instruction count, are the binding resource). Instead, cut
// cross-warp fragment duplication with a bigger tile: CTA 256x256, 512 thr,
// 4x4 warp grid, 64x64 warp tiles. Crossbar/chunk = 320KB/128B = 2500 cyc
// vs MMA 4096 cyc -> tensor-bound (R6 was 1040 vs 1024, crossbar-bound).

#include <cuda_runtime.h>
#include <cstdint>

#define DIN  4096
#define DOUT 4096
#define RNK  8
#define MTOT 8192   // 4 * 2048 rows of x

// ---- static device scratch (allocation-free) ----
__device__ float g_UT[RNK * DIN];            // normalized u^T [8][4096]
__device__ float g_T[64];                    // WY T matrix
__device__ float g_Wp[(size_t)DOUT * DIN];   // W' (tf32-rounded)
__device__ float g_Xr[(size_t)MTOT * DIN];   // x  (tf32-rounded)

// ============================ helpers ============================

static __device__ __forceinline__ uint32_t smem_u32(const void* p) {
    uint32_t a;
    asm("{ .reg .u64 t; cvta.to.shared.u64 t, %1; cvt.u32.u64 %0, t; }"
        : "=r"(a) : "l"(p));
    return a;
}

static __device__ __forceinline__ uint32_t tf32r(float f) {
    uint32_t u;
    asm("cvt.rna.tf32.f32 %0, %1;" : "=r"(u) : "f"(f));
    return u;
}

// ============================ P0: round x to tf32 ============================

__global__ void __launch_bounds__(256)
p0_round(const float* __restrict__ x) {
    size_t i = ((size_t)blockIdx.x * 256 + threadIdx.x) * 4;
    float4 v = *(const float4*)(x + i);
    uint4 u;
    u.x = tf32r(v.x); u.y = tf32r(v.y); u.z = tf32r(v.z); u.w = tf32r(v.w);
    *(uint4*)(g_Xr + i) = u;
}

// ============================ P1: normalize + Gram + T ============================

__global__ void __launch_bounds__(512)
p1_kernel(const float* __restrict__ hu) {
    __shared__ float s_rn[8];
    __shared__ float s_G[64];
    const int tid = threadIdx.x, wid = tid >> 5, lid = tid & 31;

    if (wid < 8) {
        float s = 0.f;
        for (int k = lid; k < DIN; k += 32) {
            float v = hu[(size_t)k * RNK + wid];
            s += v * v;
        }
        #pragma unroll
        for (int o = 16; o; o >>= 1) s += __shfl_xor_sync(0xFFFFFFFFu, s, o);
        if (lid == 0) s_rn[wid] = rsqrtf(s);
    }
    __syncthreads();

    for (int idx = tid; idx < RNK * DIN; idx += 512) {
        int i = idx >> 12, k = idx & (DIN - 1);
        g_UT[idx] = hu[(size_t)k * RNK + i] * s_rn[i];
    }
    __syncthreads();

    for (int p = wid; p < 36; p += 16) {
        int i = 0, rem = p;
        while (rem >= RNK - i) { rem -= RNK - i; i++; }
        int jj = i + rem;
        float s = 0.f;
        for (int k = lid; k < DIN; k += 32)
            s += g_UT[i * DIN + k] * g_UT[jj * DIN + k];
        #pragma unroll
        for (int o = 16; o; o >>= 1) s += __shfl_xor_sync(0xFFFFFFFFu, s, o);
        if (lid == 0) { s_G[i * 8 + jj] = s; s_G[jj * 8 + i] = s; }
    }
    __syncthreads();

    if (tid == 0) {
        float T[64];
        #pragma unroll
        for (int m = 0; m < 64; m++) T[m] = 0.f;
        T[0] = 2.f;
        for (int k = 1; k < 8; k++) {
            for (int i = 0; i < k; i++) {
                float s = 0.f;
                for (int m2 = i; m2 < k; m2++) s += T[i * 8 + m2] * s_G[m2 * 8 + k];
                T[i * 8 + k] = -2.f * s;
            }
            T[k * 8 + k] = 2.f;
        }
        for (int m = 0; m < 64; m++) g_T[m] = T[m];
    }
}

// ============================ P2: W' = W - (W U) T U^T ============================

static constexpr int P2_SMEM = (RNK * DIN + 64) * 4;

__global__ void __launch_bounds__(256)
p2_kernel(const float* __restrict__ W) {
    extern __shared__ float s[];
    float* sUT = s;
    float* sT  = s + RNK * DIN;
    const int tid = threadIdx.x;

    for (int idx = tid * 4; idx < RNK * DIN; idx += 256 * 4)
        *(float4*)(sUT + idx) = *(const float4*)(g_UT + idx);
    if (tid < 64) sT[tid] = g_T[tid];
    __syncthreads();

    const int wid = tid >> 5, lid = tid & 31;
    const int j = blockIdx.x * 8 + wid;          // one W row per warp
    const float* wr = W + (size_t)j * DIN;

    float acc[8] = {0.f, 0.f, 0.f, 0.f, 0.f, 0.f, 0.f, 0.f};
    for (int k = lid * 4; k < DIN; k += 128) {
        float4 w4 = *(const float4*)(wr + k);
        #pragma unroll
        for (int i = 0; i < 8; i++) {
            float4 u4 = *(const float4*)(sUT + i * DIN + k);
            acc[i] += w4.x * u4.x + w4.y * u4.y + w4.z * u4.z + w4.w * u4.w;
        }
    }
    #pragma unroll
    for (int o = 16; o; o >>= 1) {
        #pragma unroll
        for (int i = 0; i < 8; i++)
            acc[i] += __shfl_xor_sync(0xFFFFFFFFu, acc[i], o);
    }
    float v[8];
    #pragma unroll
    for (int i = 0; i < 8; i++) {
        float sv = 0.f;
        #pragma unroll
        for (int m = 0; m < 8; m++) sv += acc[m] * sT[m * 8 + i];
        v[i] = sv;
    }

    float* wp = g_Wp + (size_t)j * DIN;
    for (int k = lid * 4; k < DIN; k += 128) {
        float4 w4 = *(const float4*)(wr + k);
        #pragma unroll
        for (int i = 0; i < 8; i++) {
            float4 u4 = *(const float4*)(sUT + i * DIN + k);
            w4.x -= v[i] * u4.x; w4.y -= v[i] * u4.y;
            w4.z -= v[i] * u4.z; w4.w -= v[i] * u4.w;
        }
        uint4 r;                                  // round W' to tf32 (RN)
        r.x = tf32r(w4.x); r.y = tf32r(w4.y);
        r.z = tf32r(w4.z); r.w = tf32r(w4.w);
        *(uint4*)(wp + k) = r;
    }
}

// ============================ GEMM: out = Xr @ Wp^T + bias ============================

static constexpr int BM = 256, BN = 256, BK = 32, STG = 3;
static constexpr int ROWF    = 36;                  // padded row stride (floats)
static constexpr int AS_F    = BM * ROWF;           // A stage: 9216 floats
static constexpr int BS_F    = BN * ROWF;           // B stage: 9216 floats
static constexpr int STAGE_F = AS_F + BS_F;         // 18432 floats = 73728 B
static constexpr int GEMM_SMEM = STG * STAGE_F * 4; // 221184 B

// One stage: A 256x32 + B 256x32, 512 threads, 8 x 16B cp.async each.
static __device__ __forceinline__ void issue_stage(const float* gA, const float* gB,
                                                   int kc, int s, uint32_t sb, int tid) {
    uint32_t base = sb + (uint32_t)s * (STAGE_F * 4);
    #pragma unroll
    for (int j = 0; j < 4; j++) {                   // A rows 0..255
        int idx = tid + j * 512;
        int r = idx >> 3, c = idx & 7;
        uint32_t dA = base + (uint32_t)(r * (ROWF * 4) + c * 16);
        const float* sA = gA + (size_t)r * DIN + kc + c * 4;
        asm volatile("cp.async.cg.shared.global [%0], [%1], 16;"
                     :: "r"(dA), "l"(sA));
    }
    #pragma unroll
    for (int j = 0; j < 4; j++) {                   // B rows 0..255
        int idx = tid + j * 512;
        int r = idx >> 3, c = idx & 7;
        uint32_t dB = base + (uint32_t)(AS_F * 4 + r * (ROWF * 4) + c * 16);
        const float* sB = gB + (size_t)r * DIN + kc + c * 4;
        asm volatile("cp.async.cg.shared.global [%0], [%1], 16;"
                     :: "r"(dB), "l"(sB));
    }
}

#define MMA_TF32(D, A, B) \
    asm volatile("mma.sync.aligned.m16n8k8.row.col.f32.tf32.tf32.f32 " \
                 "{%0,%1,%2,%3}, {%4,%5,%6,%7}, {%8,%9}, {%0,%1,%2,%3};" \
                 : "+f"((D)[0]), "+f"((D)[1]), "+f"((D)[2]), "+f"((D)[3]) \
                 : "r"((A)[0]), "r"((A)[1]), "r"((A)[2]), "r"((A)[3]), \
                   "r"((B)[0]), "r"((B)[1]))

__global__ void __launch_bounds__(512, 1)
gemm_tf32(const float* __restrict__ bias, float* __restrict__ out) {
    extern __shared__ float smf[];
    const uint32_t sb = smem_u32(smf);
    const int tid = threadIdx.x, lane = tid & 31, warp = tid >> 5;
    const int g = lane >> 2, tig = lane & 3;
    const int wm = warp >> 2, wn = warp & 3;        // 4 x 4 warp grid
    const int m0 = blockIdx.y * BM, n0 = blockIdx.x * BN;

    const float* gA = g_Xr + (size_t)m0 * DIN;
    const float* gB = g_Wp + (size_t)n0 * DIN;

    issue_stage(gA, gB, 0, 0, sb, tid);
    asm volatile("cp.async.commit_group;" ::: "memory");
    issue_stage(gA, gB, BK, 1, sb, tid);
    asm volatile("cp.async.commit_group;" ::: "memory");

    float acc[4][8][4];                             // 64x64 warp tile
    #pragma unroll
    for (int mi = 0; mi < 4; mi++)
        #pragma unroll
        for (int ni = 0; ni < 8; ni++)
            #pragma unroll
            for (int q = 0; q < 4; q++) acc[mi][ni][q] = 0.f;

    const int NCH = DIN / BK;                       // 128 K-chunks
    for (int c = 0; c < NCH; c++) {
        asm volatile("cp.async.wait_group 1;" ::: "memory");
        __syncthreads();
        if (c + 2 < NCH) issue_stage(gA, gB, (c + 2) * BK, (c + 2) % STG, sb, tid);
        asm volatile("cp.async.commit_group;" ::: "memory");

        const float* As = smf + (c % STG) * STAGE_F;
        const float* Bs = As + AS_F;

        #pragma unroll
        for (int kk = 0; kk < 4; kk++) {
            const int cb = kk * 8 + tig;            // bank = 4g+tig+const: perm
            uint32_t a[4][4], b[8][2];
            #pragma unroll
            for (int mi = 0; mi < 4; mi++) {
                const int r0 = wm * 64 + mi * 16 + g;
                a[mi][0] = __float_as_uint(As[r0 * ROWF + cb]);
                a[mi][1] = __float_as_uint(As[(r0 + 8) * ROWF + cb]);
                a[mi][2] = __float_as_uint(As[r0 * ROWF + cb + 4]);
                a[mi][3] = __float_as_uint(As[(r0 + 8) * ROWF + cb + 4]);
            }
            #pragma unroll
            for (int ni = 0; ni < 8; ni++) {
                const int n = wn * 64 + ni * 8 + g;
                b[ni][0] = __float_as_uint(Bs[n * ROWF + cb]);
                b[ni][1] = __float_as_uint(Bs[n * ROWF + cb + 4]);
            }
            #pragma unroll
            for (int mi = 0; mi < 4; mi++)
                #pragma unroll
                for (int ni = 0; ni < 8; ni++)
                    MMA_TF32(acc[mi][ni], a[mi], b[ni]);
        }
    }

    // Epilogue: direct STG.64 per (row, 2-col) pair + bias.
    #pragma unroll
    for (int mi = 0; mi < 4; mi++) {
        const int row = m0 + wm * 64 + mi * 16 + g;
        #pragma unroll
        for (int ni = 0; ni < 8; ni++) {
            const int col = n0 + wn * 64 + ni * 8 + 2 * tig;
            const float2 bv = *(const float2*)(bias + col);
            float2 o0, o1;
            o0.x = acc[mi][ni][0] + bv.x; o0.y = acc[mi][ni][1] + bv.y;
            o1.x = acc[mi][ni][2] + bv.x; o1.y = acc[mi][ni][3] + bv.y;
            *(float2*)(out + (size_t)row * DOUT + col) = o0;
            *(float2*)(out + (size_t)(row + 8) * DOUT + col) = o1;
        }
    }
}

// ============================ launch ============================

extern "C" void kernel_launch(void* const* d_in, const int* in_sizes, int n_in,
                              void* d_out, int out_size) {
    const float* x    = (const float*)d_in[0];  // [4, 2048, 4096]
    const float* hu   = (const float*)d_in[1];  // [4096, 8]
    const float* W    = (const float*)d_in[2];  // [4096, 4096]
    const float* bias = (const float*)d_in[3];  // [4096]
    float* out = (float*)d_out;                 // [4, 2048, 4096]
    (void)in_sizes; (void)n_in; (void)out_size;

    cudaFuncSetAttribute(p2_kernel, cudaFuncAttributeMaxDynamicSharedMemorySize, P2_SMEM);
    cudaFuncSetAttribute(gemm_tf32, cudaFuncAttributeMaxDynamicSharedMemorySize, GEMM_SMEM);

    p0_round<<<(MTOT * DIN) / (256 * 4), 256>>>(x);
    p1_kernel<<<1, 512>>>(hu);
    p2_kernel<<<512, 256, P2_SMEM>>>(W);
    gemm_tf32<<<dim3(DOUT / BN, MTOT / BM), 512, GEMM_SMEM>>>(bias, out);
}

// round 11
// speedup vs baseline: 4.6705x; 4.6705x over previous
// HRALinear on GB300 (compute_103 non-'a' toolchain => NO tcgen05/TMA).
// Compact-WY Householder prep + Ampere-style tf32 mma.sync GEMM.
//
// R10: R9's 64x64 warp tile was right, but 512 thr capped regs at 128 ->
// accumulators spilled to local (L1=71%, tensor=17.8%). Now 256 threads,
// launch_bounds(256,1) -> 255-reg budget, no spill. CTA 128x256, 2x4 warp
// grid of 64x64 tiles, 4-stage cp.async (221KB smem) to ride out the
// single-CTA-per-SM sync shadow. Fragment pattern = R6's proven
// conflict-free scalar LDS (K-permute stays reverted).

#include <cuda_runtime.h>
#include <cstdint>

#define DIN  4096
#define DOUT 4096
#define RNK  8
#define MTOT 8192   // 4 * 2048 rows of x

// ---- static device scratch (allocation-free) ----
__device__ float g_UT[RNK * DIN];            // normalized u^T [8][4096]
__device__ float g_T[64];                    // WY T matrix
__device__ float g_Wp[(size_t)DOUT * DIN];   // W' (tf32-rounded)
__device__ float g_Xr[(size_t)MTOT * DIN];   // x  (tf32-rounded)

// ============================ helpers ============================

static __device__ __forceinline__ uint32_t smem_u32(const void* p) {
    uint32_t a;
    asm("{ .reg .u64 t; cvta.to.shared.u64 t, %1; cvt.u32.u64 %0, t; }"
        : "=r"(a) : "l"(p));
    return a;
}

static __device__ __forceinline__ uint32_t tf32r(float f) {
    uint32_t u;
    asm("cvt.rna.tf32.f32 %0, %1;" : "=r"(u) : "f"(f));
    return u;
}

// ============================ P0: round x to tf32 ============================

__global__ void __launch_bounds__(256)
p0_round(const float* __restrict__ x) {
    size_t i = ((size_t)blockIdx.x * 256 + threadIdx.x) * 4;
    float4 v = *(const float4*)(x + i);
    uint4 u;
    u.x = tf32r(v.x); u.y = tf32r(v.y); u.z = tf32r(v.z); u.w = tf32r(v.w);
    *(uint4*)(g_Xr + i) = u;
}

// ============================ P1: normalize + Gram + T ============================

__global__ void __launch_bounds__(512)
p1_kernel(const float* __restrict__ hu) {
    __shared__ float s_rn[8];
    __shared__ float s_G[64];
    const int tid = threadIdx.x, wid = tid >> 5, lid = tid & 31;

    if (wid < 8) {
        float s = 0.f;
        for (int k = lid; k < DIN; k += 32) {
            float v = hu[(size_t)k * RNK + wid];
            s += v * v;
        }
        #pragma unroll
        for (int o = 16; o; o >>= 1) s += __shfl_xor_sync(0xFFFFFFFFu, s, o);
        if (lid == 0) s_rn[wid] = rsqrtf(s);
    }
    __syncthreads();

    for (int idx = tid; idx < RNK * DIN; idx += 512) {
        int i = idx >> 12, k = idx & (DIN - 1);
        g_UT[idx] = hu[(size_t)k * RNK + i] * s_rn[i];
    }
    __syncthreads();

    for (int p = wid; p < 36; p += 16) {
        int i = 0, rem = p;
        while (rem >= RNK - i) { rem -= RNK - i; i++; }
        int jj = i + rem;
        float s = 0.f;
        for (int k = lid; k < DIN; k += 32)
            s += g_UT[i * DIN + k] * g_UT[jj * DIN + k];
        #pragma unroll
        for (int o = 16; o; o >>= 1) s += __shfl_xor_sync(0xFFFFFFFFu, s, o);
        if (lid == 0) { s_G[i * 8 + jj] = s; s_G[jj * 8 + i] = s; }
    }
    __syncthreads();

    if (tid == 0) {
        float T[64];
        #pragma unroll
        for (int m = 0; m < 64; m++) T[m] = 0.f;
        T[0] = 2.f;
        for (int k = 1; k < 8; k++) {
            for (int i = 0; i < k; i++) {
                float s = 0.f;
                for (int m2 = i; m2 < k; m2++) s += T[i * 8 + m2] * s_G[m2 * 8 + k];
                T[i * 8 + k] = -2.f * s;
            }
            T[k * 8 + k] = 2.f;
        }
        for (int m = 0; m < 64; m++) g_T[m] = T[m];
    }
}

// ============================ P2: W' = W - (W U) T U^T ============================

static constexpr int P2_SMEM = (RNK * DIN + 64) * 4;

__global__ void __launch_bounds__(256)
p2_kernel(const float* __restrict__ W) {
    extern __shared__ float s[];
    float* sUT = s;
    float* sT  = s + RNK * DIN;
    const int tid = threadIdx.x;

    for (int idx = tid * 4; idx < RNK * DIN; idx += 256 * 4)
        *(float4*)(sUT + idx) = *(const float4*)(g_UT + idx);
    if (tid < 64) sT[tid] = g_T[tid];
    __syncthreads();

    const int wid = tid >> 5, lid = tid & 31;
    const int j = blockIdx.x * 8 + wid;          // one W row per warp
    const float* wr = W + (size_t)j * DIN;

    float acc[8] = {0.f, 0.f, 0.f, 0.f, 0.f, 0.f, 0.f, 0.f};
    for (int k = lid * 4; k < DIN; k += 128) {
        float4 w4 = *(const float4*)(wr + k);
        #pragma unroll
        for (int i = 0; i < 8; i++) {
            float4 u4 = *(const float4*)(sUT + i * DIN + k);
            acc[i] += w4.x * u4.x + w4.y * u4.y + w4.z * u4.z + w4.w * u4.w;
        }
    }
    #pragma unroll
    for (int o = 16; o; o >>= 1) {
        #pragma unroll
        for (int i = 0; i < 8; i++)
            acc[i] += __shfl_xor_sync(0xFFFFFFFFu, acc[i], o);
    }
    float v[8];
    #pragma unroll
    for (int i = 0; i < 8; i++) {
        float sv = 0.f;
        #pragma unroll
        for (int m = 0; m < 8; m++) sv += acc[m] * sT[m * 8 + i];
        v[i] = sv;
    }

    float* wp = g_Wp + (size_t)j * DIN;
    for (int k = lid * 4; k < DIN; k += 128) {
        float4 w4 = *(const float4*)(wr + k);
        #pragma unroll
        for (int i = 0; i < 8; i++) {
            float4 u4 = *(const float4*)(sUT + i * DIN + k);
            w4.x -= v[i] * u4.x; w4.y -= v[i] * u4.y;
            w4.z -= v[i] * u4.z; w4.w -= v[i] * u4.w;
        }
        uint4 r;                                  // round W' to tf32 (RN)
        r.x = tf32r(w4.x); r.y = tf32r(w4.y);
        r.z = tf32r(w4.z); r.w = tf32r(w4.w);
        *(uint4*)(wp + k) = r;
    }
}

// ============================ GEMM: out = Xr @ Wp^T + bias ============================

static constexpr int BM = 128, BN = 256, BK = 32, STG = 4;
static constexpr int ROWF    = 36;                  // padded row stride (floats)
static constexpr int AS_F    = BM * ROWF;           // A stage: 4608 floats
static constexpr int BS_F    = BN * ROWF;           // B stage: 9216 floats
static constexpr int STAGE_F = AS_F + BS_F;         // 13824 floats = 55296 B
static constexpr int GEMM_SMEM = STG * STAGE_F * 4; // 221184 B

// One stage: A 128x32 + B 256x32, 256 threads, 12 x 16B cp.async each.
static __device__ __forceinline__ void issue_stage(const float* gA, const float* gB,
                                                   int kc, int s, uint32_t sb, int tid) {
    uint32_t base = sb + (uint32_t)s * (STAGE_F * 4);
    #pragma unroll
    for (int j = 0; j < 4; j++) {                   // A rows 0..127
        int idx = tid + j * 256;
        int r = idx >> 3, c = idx & 7;
        uint32_t dA = base + (uint32_t)(r * (ROWF * 4) + c * 16);
        const float* sA = gA + (size_t)r * DIN + kc + c * 4;
        asm volatile("cp.async.cg.shared.global [%0], [%1], 16;"
                     :: "r"(dA), "l"(sA));
    }
    #pragma unroll
    for (int j = 0; j < 8; j++) {                   // B rows 0..255
        int idx = tid + j * 256;
        int r = idx >> 3, c = idx & 7;
        uint32_t dB = base + (uint32_t)(AS_F * 4 + r * (ROWF * 4) + c * 16);
        const float* sB = gB + (size_t)r * DIN + kc + c * 4;
        asm volatile("cp.async.cg.shared.global [%0], [%1], 16;"
                     :: "r"(dB), "l"(sB));
    }
}

#define MMA_TF32(D, A, B) \
    asm volatile("mma.sync.aligned.m16n8k8.row.col.f32.tf32.tf32.f32 " \
                 "{%0,%1,%2,%3}, {%4,%5,%6,%7}, {%8,%9}, {%0,%1,%2,%3};" \
                 : "+f"((D)[0]), "+f"((D)[1]), "+f"((D)[2]), "+f"((D)[3]) \
                 : "r"((A)[0]), "r"((A)[1]), "r"((A)[2]), "r"((A)[3]), \
                   "r"((B)[0]), "r"((B)[1]))

__global__ void __launch_bounds__(256, 1)
gemm_tf32(const float* __restrict__ bias, float* __restrict__ out) {
    extern __shared__ float smf[];
    const uint32_t sb = smem_u32(smf);
    const int tid = threadIdx.x, lane = tid & 31, warp = tid >> 5;
    const int g = lane >> 2, tig = lane & 3;
    const int wm = warp >> 2, wn = warp & 3;        // 2 x 4 warp grid
    const int m0 = blockIdx.y * BM, n0 = blockIdx.x * BN;

    const float* gA = g_Xr + (size_t)m0 * DIN;
    const float* gB = g_Wp + (size_t)n0 * DIN;

    issue_stage(gA, gB, 0, 0, sb, tid);
    asm volatile("cp.async.commit_group;" ::: "memory");
    issue_stage(gA, gB, BK, 1, sb, tid);
    asm volatile("cp.async.commit_group;" ::: "memory");
    issue_stage(gA, gB, 2 * BK, 2, sb, tid);
    asm volatile("cp.async.commit_group;" ::: "memory");

    float acc[4][8][4];                             // 64x64 warp tile
    #pragma unroll
    for (int mi = 0; mi < 4; mi++)
        #pragma unroll
        for (int ni = 0; ni < 8; ni++)
            #pragma unroll
            for (int q = 0; q < 4; q++) acc[mi][ni][q] = 0.f;

    const int NCH = DIN / BK;                       // 128 K-chunks
    for (int c = 0; c < NCH; c++) {
        asm volatile("cp.async.wait_group 2;" ::: "memory");
        __syncthreads();
        if (c + 3 < NCH) issue_stage(gA, gB, (c + 3) * BK, (c + 3) % STG, sb, tid);
        asm volatile("cp.async.commit_group;" ::: "memory");

        const float* As = smf + (c % STG) * STAGE_F;
        const float* Bs = As + AS_F;

        #pragma unroll
        for (int kk = 0; kk < 4; kk++) {
            const int cb = kk * 8 + tig;            // bank = 4g+tig+const: perm
            uint32_t a[4][4], b[8][2];
            #pragma unroll
            for (int mi = 0; mi < 4; mi++) {
                const int r0 = wm * 64 + mi * 16 + g;
                a[mi][0] = __float_as_uint(As[r0 * ROWF + cb]);
                a[mi][1] = __float_as_uint(As[(r0 + 8) * ROWF + cb]);
                a[mi][2] = __float_as_uint(As[r0 * ROWF + cb + 4]);
                a[mi][3] = __float_as_uint(As[(r0 + 8) * ROWF + cb + 4]);
            }
            #pragma unroll
            for (int ni = 0; ni < 8; ni++) {
                const int n = wn * 64 + ni * 8 + g;
                b[ni][0] = __float_as_uint(Bs[n * ROWF + cb]);
                b[ni][1] = __float_as_uint(Bs[n * ROWF + cb + 4]);
            }
            #pragma unroll
            for (int mi = 0; mi < 4; mi++)
                #pragma unroll
                for (int ni = 0; ni < 8; ni++)
                    MMA_TF32(acc[mi][ni], a[mi], b[ni]);
        }
    }

    // Epilogue: direct STG.64 per (row, 2-col) pair + bias.
    #pragma unroll
    for (int mi = 0; mi < 4; mi++) {
        const int row = m0 + wm * 64 + mi * 16 + g;
        #pragma unroll
        for (int ni = 0; ni < 8; ni++) {
            const int col = n0 + wn * 64 + ni * 8 + 2 * tig;
            const float2 bv = *(const float2*)(bias + col);
            float2 o0, o1;
            o0.x = acc[mi][ni][0] + bv.x; o0.y = acc[mi][ni][1] + bv.y;
            o1.x = acc[mi][ni][2] + bv.x; o1.y = acc[mi][ni][3] + bv.y;
            *(float2*)(out + (size_t)row * DOUT + col) = o0;
            *(float2*)(out + (size_t)(row + 8) * DOUT + col) = o1;
        }
    }
}

// ============================ launch ============================

extern "C" void kernel_launch(void* const* d_in, const int* in_sizes, int n_in,
                              void* d_out, int out_size) {
    const float* x    = (const float*)d_in[0];  // [4, 2048, 4096]
    const float* hu   = (const float*)d_in[1];  // [4096, 8]
    const float* W    = (const float*)d_in[2];  // [4096, 4096]
    const float* bias = (const float*)d_in[3];  // [4096]
    float* out = (float*)d_out;                 // [4, 2048, 4096]
    (void)in_sizes; (void)n_in; (void)out_size;

    cudaFuncSetAttribute(p2_kernel, cudaFuncAttributeMaxDynamicSharedMemorySize, P2_SMEM);
    cudaFuncSetAttribute(gemm_tf32, cudaFuncAttributeMaxDynamicSharedMemorySize, GEMM_SMEM);

    p0_round<<<(MTOT * DIN) / (256 * 4), 256>>>(x);
    p1_kernel<<<1, 512>>>(hu);
    p2_kernel<<<512, 256, P2_SMEM>>>(W);
    gemm_tf32<<<dim3(DOUT / BN, MTOT / BM), 256, GEMM_SMEM>>>(bias, out);
}

// round 12
// speedup vs baseline: 4.7397x; 1.0148x over previous
// HRALinear on GB300 (compute_103 non-'a' toolchain => NO tcgen05/TMA).
// Compact-WY Householder prep + Ampere-style tf32 mma.sync GEMM.
//
// R11: R10 fixed spills+crossbar but ran 1 CTA/SM -> every barrier/wait
// fully exposed (occ=12.5%, tensor=58.3%). Now CTA 128x128, 4 warps (2x2
// grid of the same 64x64 warp tiles, regs~216), 3-stage pipeline at
// 110.6KB smem -> 2 CTAs/SM. Same warp count, but the two CTAs barrier
// independently so one CTA's sync shadow is filled by the other.
// Also: P0 deleted; A is RN-rounded to tf32 at fragment-load time
// (identical values, saves a 256MB pre-pass).

#include <cuda_runtime.h>
#include <cstdint>

#define DIN  4096
#define DOUT 4096
#define RNK  8
#define MTOT 8192   // 4 * 2048 rows of x

// ---- static device scratch (allocation-free) ----
__device__ float g_UT[RNK * DIN];            // normalized u^T [8][4096]
__device__ float g_T[64];                    // WY T matrix
__device__ float g_Wp[(size_t)DOUT * DIN];   // W' (tf32-rounded)

// ============================ helpers ============================

static __device__ __forceinline__ uint32_t smem_u32(const void* p) {
    uint32_t a;
    asm("{ .reg .u64 t; cvta.to.shared.u64 t, %1; cvt.u32.u64 %0, t; }"
        : "=r"(a) : "l"(p));
    return a;
}

static __device__ __forceinline__ uint32_t tf32r(float f) {
    uint32_t u;
    asm("cvt.rna.tf32.f32 %0, %1;" : "=r"(u) : "f"(f));
    return u;
}

// ============================ P1: normalize + Gram + T ============================

__global__ void __launch_bounds__(512)
p1_kernel(const float* __restrict__ hu) {
    __shared__ float s_rn[8];
    __shared__ float s_G[64];
    const int tid = threadIdx.x, wid = tid >> 5, lid = tid & 31;

    if (wid < 8) {
        float s = 0.f;
        for (int k = lid; k < DIN; k += 32) {
            float v = hu[(size_t)k * RNK + wid];
            s += v * v;
        }
        #pragma unroll
        for (int o = 16; o; o >>= 1) s += __shfl_xor_sync(0xFFFFFFFFu, s, o);
        if (lid == 0) s_rn[wid] = rsqrtf(s);
    }
    __syncthreads();

    for (int idx = tid; idx < RNK * DIN; idx += 512) {
        int i = idx >> 12, k = idx & (DIN - 1);
        g_UT[idx] = hu[(size_t)k * RNK + i] * s_rn[i];
    }
    __syncthreads();

    for (int p = wid; p < 36; p += 16) {
        int i = 0, rem = p;
        while (rem >= RNK - i) { rem -= RNK - i; i++; }
        int jj = i + rem;
        float s = 0.f;
        for (int k = lid; k < DIN; k += 32)
            s += g_UT[i * DIN + k] * g_UT[jj * DIN + k];
        #pragma unroll
        for (int o = 16; o; o >>= 1) s += __shfl_xor_sync(0xFFFFFFFFu, s, o);
        if (lid == 0) { s_G[i * 8 + jj] = s; s_G[jj * 8 + i] = s; }
    }
    __syncthreads();

    if (tid == 0) {
        float T[64];
        #pragma unroll
        for (int m = 0; m < 64; m++) T[m] = 0.f;
        T[0] = 2.f;
        for (int k = 1; k < 8; k++) {
            for (int i = 0; i < k; i++) {
                float s = 0.f;
                for (int m2 = i; m2 < k; m2++) s += T[i * 8 + m2] * s_G[m2 * 8 + k];
                T[i * 8 + k] = -2.f * s;
            }
            T[k * 8 + k] = 2.f;
        }
        for (int m = 0; m < 64; m++) g_T[m] = T[m];
    }
}

// ============================ P2: W' = W - (W U) T U^T ============================

static constexpr int P2_SMEM = (RNK * DIN + 64) * 4;

__global__ void __launch_bounds__(256)
p2_kernel(const float* __restrict__ W) {
    extern __shared__ float s[];
    float* sUT = s;
    float* sT  = s + RNK * DIN;
    const int tid = threadIdx.x;

    for (int idx = tid * 4; idx < RNK * DIN; idx += 256 * 4)
        *(float4*)(sUT + idx) = *(const float4*)(g_UT + idx);
    if (tid < 64) sT[tid] = g_T[tid];
    __syncthreads();

    const int wid = tid >> 5, lid = tid & 31;
    const int j = blockIdx.x * 8 + wid;          // one W row per warp
    const float* wr = W + (size_t)j * DIN;

    float acc[8] = {0.f, 0.f, 0.f, 0.f, 0.f, 0.f, 0.f, 0.f};
    for (int k = lid * 4; k < DIN; k += 128) {
        float4 w4 = *(const float4*)(wr + k);
        #pragma unroll
        for (int i = 0; i < 8; i++) {
            float4 u4 = *(const float4*)(sUT + i * DIN + k);
            acc[i] += w4.x * u4.x + w4.y * u4.y + w4.z * u4.z + w4.w * u4.w;
        }
    }
    #pragma unroll
    for (int o = 16; o; o >>= 1) {
        #pragma unroll
        for (int i = 0; i < 8; i++)
            acc[i] += __shfl_xor_sync(0xFFFFFFFFu, acc[i], o);
    }
    float v[8];
    #pragma unroll
    for (int i = 0; i < 8; i++) {
        float sv = 0.f;
        #pragma unroll
        for (int m = 0; m < 8; m++) sv += acc[m] * sT[m * 8 + i];
        v[i] = sv;
    }

    float* wp = g_Wp + (size_t)j * DIN;
    for (int k = lid * 4; k < DIN; k += 128) {
        float4 w4 = *(const float4*)(wr + k);
        #pragma unroll
        for (int i = 0; i < 8; i++) {
            float4 u4 = *(const float4*)(sUT + i * DIN + k);
            w4.x -= v[i] * u4.x; w4.y -= v[i] * u4.y;
            w4.z -= v[i] * u4.z; w4.w -= v[i] * u4.w;
        }
        uint4 r;                                  // round W' to tf32 (RN)
        r.x = tf32r(w4.x); r.y = tf32r(w4.y);
        r.z = tf32r(w4.z); r.w = tf32r(w4.w);
        *(uint4*)(wp + k) = r;
    }
}

// ============================ GEMM: out = x @ Wp^T + bias ============================

static constexpr int BM = 128, BN = 128, BK = 32, STG = 3;
static constexpr int ROWF    = 36;                  // padded row stride (floats)
static constexpr int AS_F    = BM * ROWF;           // A stage: 4608 floats
static constexpr int BS_F    = BN * ROWF;           // B stage: 4608 floats
static constexpr int STAGE_F = AS_F + BS_F;         // 9216 floats = 36864 B
static constexpr int GEMM_SMEM = STG * STAGE_F * 4; // 110592 B (2 CTAs/SM)

// One stage: A 128x32 + B 128x32, 128 threads, 16 x 16B cp.async each.
static __device__ __forceinline__ void issue_stage(const float* gA, const float* gB,
                                                   int kc, int s, uint32_t sb, int tid) {
    uint32_t base = sb + (uint32_t)s * (STAGE_F * 4);
    #pragma unroll
    for (int j = 0; j < 8; j++) {                   // A rows 0..127 (raw x)
        int idx = tid + j * 128;
        int r = idx >> 3, c = idx & 7;
        uint32_t dA = base + (uint32_t)(r * (ROWF * 4) + c * 16);
        const float* sA = gA + (size_t)r * DIN + kc + c * 4;
        asm volatile("cp.async.cg.shared.global [%0], [%1], 16;"
                     :: "r"(dA), "l"(sA));
    }
    #pragma unroll
    for (int j = 0; j < 8; j++) {                   // B rows 0..127 (pre-rounded W')
        int idx = tid + j * 128;
        int r = idx >> 3, c = idx & 7;
        uint32_t dB = base + (uint32_t)(AS_F * 4 + r * (ROWF * 4) + c * 16);
        const float* sB = gB + (size_t)r * DIN + kc + c * 4;
        asm volatile("cp.async.cg.shared.global [%0], [%1], 16;"
                     :: "r"(dB), "l"(sB));
    }
}

#define MMA_TF32(D, A, B) \
    asm volatile("mma.sync.aligned.m16n8k8.row.col.f32.tf32.tf32.f32 " \
                 "{%0,%1,%2,%3}, {%4,%5,%6,%7}, {%8,%9}, {%0,%1,%2,%3};" \
                 : "+f"((D)[0]), "+f"((D)[1]), "+f"((D)[2]), "+f"((D)[3]) \
                 : "r"((A)[0]), "r"((A)[1]), "r"((A)[2]), "r"((A)[3]), \
                   "r"((B)[0]), "r"((B)[1]))

__global__ void __launch_bounds__(128, 2)
gemm_tf32(const float* __restrict__ x, const float* __restrict__ bias,
          float* __restrict__ out) {
    extern __shared__ float smf[];
    const uint32_t sb = smem_u32(smf);
    const int tid = threadIdx.x, lane = tid & 31, warp = tid >> 5;
    const int g = lane >> 2, tig = lane & 3;
    const int wm = warp >> 1, wn = warp & 1;        // 2 x 2 warp grid
    const int m0 = blockIdx.y * BM, n0 = blockIdx.x * BN;

    const float* gA = x + (size_t)m0 * DIN;
    const float* gB = g_Wp + (size_t)n0 * DIN;

    issue_stage(gA, gB, 0, 0, sb, tid);
    asm volatile("cp.async.commit_group;" ::: "memory");
    issue_stage(gA, gB, BK, 1, sb, tid);
    asm volatile("cp.async.commit_group;" ::: "memory");

    float acc[4][8][4];                             // 64x64 warp tile
    #pragma unroll
    for (int mi = 0; mi < 4; mi++)
        #pragma unroll
        for (int ni = 0; ni < 8; ni++)
            #pragma unroll
            for (int q = 0; q < 4; q++) acc[mi][ni][q] = 0.f;

    const int NCH = DIN / BK;                       // 128 K-chunks
    for (int c = 0; c < NCH; c++) {
        asm volatile("cp.async.wait_group 1;" ::: "memory");
        __syncthreads();
        if (c + 2 < NCH) issue_stage(gA, gB, (c + 2) * BK, (c + 2) % STG, sb, tid);
        asm volatile("cp.async.commit_group;" ::: "memory");

        const float* As = smf + (c % STG) * STAGE_F;
        const float* Bs = As + AS_F;

        #pragma unroll
        for (int kk = 0; kk < 4; kk++) {
            const int cb = kk * 8 + tig;            // bank = 4g+tig+const: perm
            uint32_t a[4][4], b[8][2];
            #pragma unroll
            for (int mi = 0; mi < 4; mi++) {
                const int r0 = wm * 64 + mi * 16 + g;
                a[mi][0] = tf32r(As[r0 * ROWF + cb]);        // RN-round raw x
                a[mi][1] = tf32r(As[(r0 + 8) * ROWF + cb]);
                a[mi][2] = tf32r(As[r0 * ROWF + cb + 4]);
                a[mi][3] = tf32r(As[(r0 + 8) * ROWF + cb + 4]);
            }
            #pragma unroll
            for (int ni = 0; ni < 8; ni++) {
                const int n = wn * 64 + ni * 8 + g;
                b[ni][0] = __float_as_uint(Bs[n * ROWF + cb]);
                b[ni][1] = __float_as_uint(Bs[n * ROWF + cb + 4]);
            }
            #pragma unroll
            for (int mi = 0; mi < 4; mi++)
                #pragma unroll
                for (int ni = 0; ni < 8; ni++)
                    MMA_TF32(acc[mi][ni], a[mi], b[ni]);
        }
    }

    // Epilogue: direct STG.64 per (row, 2-col) pair + bias.
    #pragma unroll
    for (int mi = 0; mi < 4; mi++) {
        const int row = m0 + wm * 64 + mi * 16 + g;
        #pragma unroll
        for (int ni = 0; ni < 8; ni++) {
            const int col = n0 + wn * 64 + ni * 8 + 2 * tig;
            const float2 bv = *(const float2*)(bias + col);
            float2 o0, o1;
            o0.x = acc[mi][ni][0] + bv.x; o0.y = acc[mi][ni][1] + bv.y;
            o1.x = acc[mi][ni][2] + bv.x; o1.y = acc[mi][ni][3] + bv.y;
            *(float2*)(out + (size_t)row * DOUT + col) = o0;
            *(float2*)(out + (size_t)(row + 8) * DOUT + col) = o1;
        }
    }
}

// ============================ launch ============================

extern "C" void kernel_launch(void* const* d_in, const int* in_sizes, int n_in,
                              void* d_out, int out_size) {
    const float* x    = (const float*)d_in[0];  // [4, 2048, 4096]
    const float* hu   = (const float*)d_in[1];  // [4096, 8]
    const float* W    = (const float*)d_in[2];  // [4096, 4096]
    const float* bias = (const float*)d_in[3];  // [4096]
    float* out = (float*)d_out;                 // [4, 2048, 4096]
    (void)in_sizes; (void)n_in; (void)out_size;

    cudaFuncSetAttribute(p2_kernel, cudaFuncAttributeMaxDynamicSharedMemorySize, P2_SMEM);
    cudaFuncSetAttribute(gemm_tf32, cudaFuncAttributeMaxDynamicSharedMemorySize, GEMM_SMEM);

    p1_kernel<<<1, 512>>>(hu);
    p2_kernel<<<512, 256, P2_SMEM>>>(W);
    gemm_tf32<<<dim3(DOUT / BN, MTOT / BM), 128, GEMM_SMEM>>>(x, bias, out);
}

// round 13
// speedup vs baseline: 4.7820x; 1.0089x over previous
// HRALinear on GB300 (compute_103 non-'a' toolchain => NO tcgen05/TMA).
// Compact-WY Householder prep + Ampere-style tf32 mma.sync GEMM.
//
// R13: explicit double-buffered FRAGMENTS. R6/R10/R11 all pinned tensor at
// ~58-60%: the 4 kk-subblocks serialize (fragment regs reused -> WAR), so
// each kk pays LDS issue + 29cyc LDS lat + cvt before its 256-cyc MMA
// block (~1460 cyc/chunk vs 1024 floor). Now a[2][4][4]/b[2][8][2]: kk+1
// loads target the idle buffer and schedule under kk's MMAs. Frag LDS for
// kk=0 issues BEFORE the cp.async prefetch (LDGSTS rt=8 contends MIO).
// Everything else = R11 (128x128 CTA, 4 warps, 64x64 warp tile, 3-stage
// cp.async, 2 CTAs/SM, in-loop cvt.rna.tf32 on A).

#include <cuda_runtime.h>
#include <cstdint>

#define DIN  4096
#define DOUT 4096
#define RNK  8
#define MTOT 8192   // 4 * 2048 rows of x

// ---- static device scratch (allocation-free) ----
__device__ float g_UT[RNK * DIN];            // normalized u^T [8][4096]
__device__ float g_T[64];                    // WY T matrix
__device__ float g_Wp[(size_t)DOUT * DIN];   // W' (tf32-rounded)

// ============================ helpers ============================

static __device__ __forceinline__ uint32_t smem_u32(const void* p) {
    uint32_t a;
    asm("{ .reg .u64 t; cvta.to.shared.u64 t, %1; cvt.u32.u64 %0, t; }"
        : "=r"(a) : "l"(p));
    return a;
}

static __device__ __forceinline__ uint32_t tf32r(float f) {
    uint32_t u;
    asm("cvt.rna.tf32.f32 %0, %1;" : "=r"(u) : "f"(f));
    return u;
}

// ============================ P1: normalize + Gram + T ============================

__global__ void __launch_bounds__(512)
p1_kernel(const float* __restrict__ hu) {
    __shared__ float s_rn[8];
    __shared__ float s_G[64];
    const int tid = threadIdx.x, wid = tid >> 5, lid = tid & 31;

    if (wid < 8) {
        float s = 0.f;
        for (int k = lid; k < DIN; k += 32) {
            float v = hu[(size_t)k * RNK + wid];
            s += v * v;
        }
        #pragma unroll
        for (int o = 16; o; o >>= 1) s += __shfl_xor_sync(0xFFFFFFFFu, s, o);
        if (lid == 0) s_rn[wid] = rsqrtf(s);
    }
    __syncthreads();

    for (int idx = tid; idx < RNK * DIN; idx += 512) {
        int i = idx >> 12, k = idx & (DIN - 1);
        g_UT[idx] = hu[(size_t)k * RNK + i] * s_rn[i];
    }
    __syncthreads();

    for (int p = wid; p < 36; p += 16) {
        int i = 0, rem = p;
        while (rem >= RNK - i) { rem -= RNK - i; i++; }
        int jj = i + rem;
        float s = 0.f;
        for (int k = lid; k < DIN; k += 32)
            s += g_UT[i * DIN + k] * g_UT[jj * DIN + k];
        #pragma unroll
        for (int o = 16; o; o >>= 1) s += __shfl_xor_sync(0xFFFFFFFFu, s, o);
        if (lid == 0) { s_G[i * 8 + jj] = s; s_G[jj * 8 + i] = s; }
    }
    __syncthreads();

    if (tid == 0) {
        float T[64];
        #pragma unroll
        for (int m = 0; m < 64; m++) T[m] = 0.f;
        T[0] = 2.f;
        for (int k = 1; k < 8; k++) {
            for (int i = 0; i < k; i++) {
                float s = 0.f;
                for (int m2 = i; m2 < k; m2++) s += T[i * 8 + m2] * s_G[m2 * 8 + k];
                T[i * 8 + k] = -2.f * s;
            }
            T[k * 8 + k] = 2.f;
        }
        for (int m = 0; m < 64; m++) g_T[m] = T[m];
    }
}

// ============================ P2: W' = W - (W U) T U^T ============================

static constexpr int P2_SMEM = (RNK * DIN + 64) * 4;

__global__ void __launch_bounds__(256)
p2_kernel(const float* __restrict__ W) {
    extern __shared__ float s[];
    float* sUT = s;
    float* sT  = s + RNK * DIN;
    const int tid = threadIdx.x;

    for (int idx = tid * 4; idx < RNK * DIN; idx += 256 * 4)
        *(float4*)(sUT + idx) = *(const float4*)(g_UT + idx);
    if (tid < 64) sT[tid] = g_T[tid];
    __syncthreads();

    const int wid = tid >> 5, lid = tid & 31;
    const int j = blockIdx.x * 8 + wid;          // one W row per warp
    const float* wr = W + (size_t)j * DIN;

    float acc[8] = {0.f, 0.f, 0.f, 0.f, 0.f, 0.f, 0.f, 0.f};
    for (int k = lid * 4; k < DIN; k += 128) {
        float4 w4 = *(const float4*)(wr + k);
        #pragma unroll
        for (int i = 0; i < 8; i++) {
            float4 u4 = *(const float4*)(sUT + i * DIN + k);
            acc[i] += w4.x * u4.x + w4.y * u4.y + w4.z * u4.z + w4.w * u4.w;
        }
    }
    #pragma unroll
    for (int o = 16; o; o >>= 1) {
        #pragma unroll
        for (int i = 0; i < 8; i++)
            acc[i] += __shfl_xor_sync(0xFFFFFFFFu, acc[i], o);
    }
    float v[8];
    #pragma unroll
    for (int i = 0; i < 8; i++) {
        float sv = 0.f;
        #pragma unroll
        for (int m = 0; m < 8; m++) sv += acc[m] * sT[m * 8 + i];
        v[i] = sv;
    }

    float* wp = g_Wp + (size_t)j * DIN;
    for (int k = lid * 4; k < DIN; k += 128) {
        float4 w4 = *(const float4*)(wr + k);
        #pragma unroll
        for (int i = 0; i < 8; i++) {
            float4 u4 = *(const float4*)(sUT + i * DIN + k);
            w4.x -= v[i] * u4.x; w4.y -= v[i] * u4.y;
            w4.z -= v[i] * u4.z; w4.w -= v[i] * u4.w;
        }
        uint4 r;                                  // round W' to tf32 (RN)
        r.x = tf32r(w4.x); r.y = tf32r(w4.y);
        r.z = tf32r(w4.z); r.w = tf32r(w4.w);
        *(uint4*)(wp + k) = r;
    }
}

// ============================ GEMM: out = x @ Wp^T + bias ============================

static constexpr int BM = 128, BN = 128, BK = 32, STG = 3;
static constexpr int ROWF    = 36;                  // padded row stride (floats)
static constexpr int AS_F    = BM * ROWF;           // A stage: 4608 floats
static constexpr int BS_F    = BN * ROWF;           // B stage: 4608 floats
static constexpr int STAGE_F = AS_F + BS_F;         // 9216 floats = 36864 B
static constexpr int GEMM_SMEM = STG * STAGE_F * 4; // 110592 B (2 CTAs/SM)

// One stage: A 128x32 + B 128x32, 128 threads, 16 x 16B cp.async each.
static __device__ __forceinline__ void issue_stage(const float* gA, const float* gB,
                                                   int kc, int s, uint32_t sb, int tid) {
    uint32_t base = sb + (uint32_t)s * (STAGE_F * 4);
    #pragma unroll
    for (int j = 0; j < 8; j++) {                   // A rows 0..127 (raw x)
        int idx = tid + j * 128;
        int r = idx >> 3, c = idx & 7;
        uint32_t dA = base + (uint32_t)(r * (ROWF * 4) + c * 16);
        const float* sA = gA + (size_t)r * DIN + kc + c * 4;
        asm volatile("cp.async.cg.shared.global [%0], [%1], 16;"
                     :: "r"(dA), "l"(sA));
    }
    #pragma unroll
    for (int j = 0; j < 8; j++) {                   // B rows 0..127 (pre-rounded W')
        int idx = tid + j * 128;
        int r = idx >> 3, c = idx & 7;
        uint32_t dB = base + (uint32_t)(AS_F * 4 + r * (ROWF * 4) + c * 16);
        const float* sB = gB + (size_t)r * DIN + kc + c * 4;
        asm volatile("cp.async.cg.shared.global [%0], [%1], 16;"
                     :: "r"(dB), "l"(sB));
    }
}

#define MMA_TF32(D, A, B) \
    asm volatile("mma.sync.aligned.m16n8k8.row.col.f32.tf32.tf32.f32 " \
                 "{%0,%1,%2,%3}, {%4,%5,%6,%7}, {%8,%9}, {%0,%1,%2,%3};" \
                 : "+f"((D)[0]), "+f"((D)[1]), "+f"((D)[2]), "+f"((D)[3]) \
                 : "r"((A)[0]), "r"((A)[1]), "r"((A)[2]), "r"((A)[3]), \
                   "r"((B)[0]), "r"((B)[1]))

// Load one kk-step's fragments into buffer `buf`.
#define LOAD_FRAGS(As, Bs, kk, buf) do {                                     \
    const int cb_ = (kk) * 8 + tig;                                          \
    _Pragma("unroll")                                                        \
    for (int mi = 0; mi < 4; mi++) {                                         \
        const int r0_ = wm * 64 + mi * 16 + g;                               \
        a[buf][mi][0] = tf32r((As)[r0_ * ROWF + cb_]);                       \
        a[buf][mi][1] = tf32r((As)[(r0_ + 8) * ROWF + cb_]);                 \
        a[buf][mi][2] = tf32r((As)[r0_ * ROWF + cb_ + 4]);                   \
        a[buf][mi][3] = tf32r((As)[(r0_ + 8) * ROWF + cb_ + 4]);             \
    }                                                                        \
    _Pragma("unroll")                                                        \
    for (int ni = 0; ni < 8; ni++) {                                         \
        const int n_ = wn * 64 + ni * 8 + g;                                 \
        b[buf][ni][0] = __float_as_uint((Bs)[n_ * ROWF + cb_]);              \
        b[buf][ni][1] = __float_as_uint((Bs)[n_ * ROWF + cb_ + 4]);          \
    }                                                                        \
} while (0)

__global__ void __launch_bounds__(128, 2)
gemm_tf32(const float* __restrict__ x, const float* __restrict__ bias,
          float* __restrict__ out) {
    extern __shared__ float smf[];
    const uint32_t sb = smem_u32(smf);
    const int tid = threadIdx.x, lane = tid & 31, warp = tid >> 5;
    const int g = lane >> 2, tig = lane & 3;
    const int wm = warp >> 1, wn = warp & 1;        // 2 x 2 warp grid
    const int m0 = blockIdx.y * BM, n0 = blockIdx.x * BN;

    const float* gA = x + (size_t)m0 * DIN;
    const float* gB = g_Wp + (size_t)n0 * DIN;

    issue_stage(gA, gB, 0, 0, sb, tid);
    asm volatile("cp.async.commit_group;" ::: "memory");
    issue_stage(gA, gB, BK, 1, sb, tid);
    asm volatile("cp.async.commit_group;" ::: "memory");

    float acc[4][8][4];                             // 64x64 warp tile
    #pragma unroll
    for (int mi = 0; mi < 4; mi++)
        #pragma unroll
        for (int ni = 0; ni < 8; ni++)
            #pragma unroll
            for (int q = 0; q < 4; q++) acc[mi][ni][q] = 0.f;

    uint32_t a[2][4][4], b[2][8][2];                // double-buffered fragments

    const int NCH = DIN / BK;                       // 128 K-chunks
    for (int c = 0; c < NCH; c++) {
        asm volatile("cp.async.wait_group 1;" ::: "memory");
        __syncthreads();

        const float* As = smf + (c % STG) * STAGE_F;
        const float* Bs = As + AS_F;

        // Critical-path first: kk=0 fragment LDS before the LDGSTS burst.
        LOAD_FRAGS(As, Bs, 0, 0);

        if (c + 2 < NCH) issue_stage(gA, gB, (c + 2) * BK, (c + 2) % STG, sb, tid);
        asm volatile("cp.async.commit_group;" ::: "memory");

        #pragma unroll
        for (int kk = 0; kk < 4; kk++) {
            const int cur = kk & 1;
            if (kk < 3) {                            // prefetch into idle buffer
                const int nxt = (kk + 1) & 1;
                LOAD_FRAGS(As, Bs, kk + 1, nxt);
            }
            #pragma unroll
            for (int mi = 0; mi < 4; mi++)
                #pragma unroll
                for (int ni = 0; ni < 8; ni++)
                    MMA_TF32(acc[mi][ni], a[cur][mi], b[cur][ni]);
        }
    }

    // Epilogue: direct STG.64 per (row, 2-col) pair + bias.
    #pragma unroll
    for (int mi = 0; mi < 4; mi++) {
        const int row = m0 + wm * 64 + mi * 16 + g;
        #pragma unroll
        for (int ni = 0; ni < 8; ni++) {
            const int col = n0 + wn * 64 + ni * 8 + 2 * tig;
            const float2 bv = *(const float2*)(bias + col);
            float2 o0, o1;
            o0.x = acc[mi][ni][0] + bv.x; o0.y = acc[mi][ni][1] + bv.y;
            o1.x = acc[mi][ni][2] + bv.x; o1.y = acc[mi][ni][3] + bv.y;
            *(float2*)(out + (size_t)row * DOUT + col) = o0;
            *(float2*)(out + (size_t)(row + 8) * DOUT + col) = o1;
        }
    }
}

// ============================ launch ============================

extern "C" void kernel_launch(void* const* d_in, const int* in_sizes, int n_in,
                              void* d_out, int out_size) {
    const float* x    = (const float*)d_in[0];  // [4, 2048, 4096]
    const float* hu   = (const float*)d_in[1];  // [4096, 8]
    const float* W    = (const float*)d_in[2];  // [4096, 4096]
    const float* bias = (const float*)d_in[3];  // [4096]
    float* out = (float*)d_out;                 // [4, 2048, 4096]
    (void)in_sizes; (void)n_in; (void)out_size;

    cudaFuncSetAttribute(p2_kernel, cudaFuncAttributeMaxDynamicSharedMemorySize, P2_SMEM);
    cudaFuncSetAttribute(gemm_tf32, cudaFuncAttributeMaxDynamicSharedMemorySize, GEMM_SMEM);

    p1_kernel<<<1, 512>>>(hu);
    p2_kernel<<<512, 256, P2_SMEM>>>(W);
    gemm_tf32<<<dim3(DOUT / BN, MTOT / BM), 128, GEMM_SMEM>>>(x, bias, out);
}

// round 14
// speedup vs baseline: 5.0038x; 1.0464x over previous
// HRALinear on GB300 (compute_103 non-'a' toolchain => NO tcgen05/TMA).
// Compact-WY Householder prep + Ampere-style tf32 mma.sync GEMM.
//
// R14: issue-port relief. Audit: per warp/chunk 128 HMMA + 96 LDS + 64 CVT
// + 16 LDGSTS + ~20 ovh ~= 904/1024 SMSP issue-cycles -> any bubble lands
// on the tensor pipe (58% plateau across all warp/CTA configs). Changes:
//  1) P0 pre-round restored (x -> g_Xr once, ~38us): removes all 64
//     in-loop cvt.rna.tf32 issues from the GEMM critical path.
//  2) p1 parallelized (was 37us on ONE block): p1a norms (8 blocks),
//     p1b Gram pairs (36 blocks), p1c T build (1 thread). ~13us.
//  3) GEMM otherwise = R13 (128x128 CTA, 4 warps, 64x64 warp tiles,
//     3-stage cp.async, 2 CTAs/SM, double-buffered fragments).

#include <cuda_runtime.h>
#include <cstdint>

#define DIN  4096
#define DOUT 4096
#define RNK  8
#define MTOT 8192   // 4 * 2048 rows of x

// ---- static device scratch (allocation-free) ----
__device__ float g_UT[RNK * DIN];            // normalized u^T [8][4096]
__device__ float g_G[64];                    // Gram matrix
__device__ float g_T[64];                    // WY T matrix
__device__ float g_Wp[(size_t)DOUT * DIN];   // W' (tf32-rounded)
__device__ float g_Xr[(size_t)MTOT * DIN];   // x  (tf32-rounded)

// ============================ helpers ============================

static __device__ __forceinline__ uint32_t smem_u32(const void* p) {
    uint32_t a;
    asm("{ .reg .u64 t; cvta.to.shared.u64 t, %1; cvt.u32.u64 %0, t; }"
        : "=r"(a) : "l"(p));
    return a;
}

static __device__ __forceinline__ uint32_t tf32r(float f) {
    uint32_t u;
    asm("cvt.rna.tf32.f32 %0, %1;" : "=r"(u) : "f"(f));
    return u;
}

// ============================ P0: round x to tf32 ============================

__global__ void __launch_bounds__(256)
p0_round(const float* __restrict__ x) {
    size_t i = ((size_t)blockIdx.x * 256 + threadIdx.x) * 4;
    float4 v = *(const float4*)(x + i);
    uint4 u;
    u.x = tf32r(v.x); u.y = tf32r(v.y); u.z = tf32r(v.z); u.w = tf32r(v.w);
    *(uint4*)(g_Xr + i) = u;
}

// ============================ P1a: normalize u columns (8 blocks) ============================

__global__ void __launch_bounds__(256)
p1a_norm(const float* __restrict__ hu) {
    __shared__ float s_part[8];
    const int i = blockIdx.x;                 // column 0..7
    const int tid = threadIdx.x, wid = tid >> 5, lid = tid & 31;

    float s = 0.f;
    for (int k = tid; k < DIN; k += 256) {
        float v = hu[(size_t)k * RNK + i];
        s += v * v;
    }
    #pragma unroll
    for (int o = 16; o; o >>= 1) s += __shfl_xor_sync(0xFFFFFFFFu, s, o);
    if (lid == 0) s_part[wid] = s;
    __syncthreads();
    if (tid == 0) {
        float t = 0.f;
        #pragma unroll
        for (int w = 0; w < 8; w++) t += s_part[w];
        s_part[0] = rsqrtf(t);
    }
    __syncthreads();
    const float rn = s_part[0];
    for (int k = tid; k < DIN; k += 256)
        g_UT[i * DIN + k] = hu[(size_t)k * RNK + i] * rn;
}

// ============================ P1b: Gram pairs (36 blocks, 1 warp) ============================

__global__ void __launch_bounds__(32)
p1b_gram() {
    const int p = blockIdx.x;                 // pair index 0..35
    int i = 0, rem = p;
    while (rem >= RNK - i) { rem -= RNK - i; i++; }
    const int jj = i + rem;
    const int lid = threadIdx.x;

    float s = 0.f;
    for (int k = lid * 4; k < DIN; k += 128) {
        float4 a4 = *(const float4*)(g_UT + i * DIN + k);
        float4 b4 = *(const float4*)(g_UT + jj * DIN + k);
        s += a4.x * b4.x + a4.y * b4.y + a4.z * b4.z + a4.w * b4.w;
    }
    #pragma unroll
    for (int o = 16; o; o >>= 1) s += __shfl_xor_sync(0xFFFFFFFFu, s, o);
    if (lid == 0) { g_G[i * 8 + jj] = s; g_G[jj * 8 + i] = s; }
}

// ============================ P1c: WY T matrix (1 thread) ============================

__global__ void p1c_buildT() {
    if (threadIdx.x != 0 || blockIdx.x != 0) return;
    float T[64];
    #pragma unroll
    for (int m = 0; m < 64; m++) T[m] = 0.f;
    T[0] = 2.f;
    for (int k = 1; k < 8; k++) {
        for (int i = 0; i < k; i++) {
            float s = 0.f;
            for (int m2 = i; m2 < k; m2++) s += T[i * 8 + m2] * g_G[m2 * 8 + k];
            T[i * 8 + k] = -2.f * s;
        }
        T[k * 8 + k] = 2.f;
    }
    for (int m = 0; m < 64; m++) g_T[m] = T[m];
}

// ============================ P2: W' = W - (W U) T U^T ============================

static constexpr int P2_SMEM = (RNK * DIN + 64) * 4;

__global__ void __launch_bounds__(256)
p2_kernel(const float* __restrict__ W) {
    extern __shared__ float s[];
    float* sUT = s;
    float* sT  = s + RNK * DIN;
    const int tid = threadIdx.x;

    for (int idx = tid * 4; idx < RNK * DIN; idx += 256 * 4)
        *(float4*)(sUT + idx) = *(const float4*)(g_UT + idx);
    if (tid < 64) sT[tid] = g_T[tid];
    __syncthreads();

    const int wid = tid >> 5, lid = tid & 31;
    const int j = blockIdx.x * 8 + wid;          // one W row per warp
    const float* wr = W + (size_t)j * DIN;

    float acc[8] = {0.f, 0.f, 0.f, 0.f, 0.f, 0.f, 0.f, 0.f};
    for (int k = lid * 4; k < DIN; k += 128) {
        float4 w4 = *(const float4*)(wr + k);
        #pragma unroll
        for (int i = 0; i < 8; i++) {
            float4 u4 = *(const float4*)(sUT + i * DIN + k);
            acc[i] += w4.x * u4.x + w4.y * u4.y + w4.z * u4.z + w4.w * u4.w;
        }
    }
    #pragma unroll
    for (int o = 16; o; o >>= 1) {
        #pragma unroll
        for (int i = 0; i < 8; i++)
            acc[i] += __shfl_xor_sync(0xFFFFFFFFu, acc[i], o);
    }
    float v[8];
    #pragma unroll
    for (int i = 0; i < 8; i++) {
        float sv = 0.f;
        #pragma unroll
        for (int m = 0; m < 8; m++) sv += acc[m] * sT[m * 8 + i];
        v[i] = sv;
    }

    float* wp = g_Wp + (size_t)j * DIN;
    for (int k = lid * 4; k < DIN; k += 128) {
        float4 w4 = *(const float4*)(wr + k);
        #pragma unroll
        for (int i = 0; i < 8; i++) {
            float4 u4 = *(const float4*)(sUT + i * DIN + k);
            w4.x -= v[i] * u4.x; w4.y -= v[i] * u4.y;
            w4.z -= v[i] * u4.z; w4.w -= v[i] * u4.w;
        }
        uint4 r;                                  // round W' to tf32 (RN)
        r.x = tf32r(w4.x); r.y = tf32r(w4.y);
        r.z = tf32r(w4.z); r.w = tf32r(w4.w);
        *(uint4*)(wp + k) = r;
    }
}

// ============================ GEMM: out = Xr @ Wp^T + bias ============================

static constexpr int BM = 128, BN = 128, BK = 32, STG = 3;
static constexpr int ROWF    = 36;                  // padded row stride (floats)
static constexpr int AS_F    = BM * ROWF;           // A stage: 4608 floats
static constexpr int BS_F    = BN * ROWF;           // B stage: 4608 floats
static constexpr int STAGE_F = AS_F + BS_F;         // 9216 floats = 36864 B
static constexpr int GEMM_SMEM = STG * STAGE_F * 4; // 110592 B (2 CTAs/SM)

// One stage: A 128x32 + B 128x32, 128 threads, 16 x 16B cp.async each.
static __device__ __forceinline__ void issue_stage(const float* gA, const float* gB,
                                                   int kc, int s, uint32_t sb, int tid) {
    uint32_t base = sb + (uint32_t)s * (STAGE_F * 4);
    #pragma unroll
    for (int j = 0; j < 8; j++) {                   // A rows 0..127 (pre-rounded x)
        int idx = tid + j * 128;
        int r = idx >> 3, c = idx & 7;
        uint32_t dA = base + (uint32_t)(r * (ROWF * 4) + c * 16);
        const float* sA = gA + (size_t)r * DIN + kc + c * 4;
        asm volatile("cp.async.cg.shared.global [%0], [%1], 16;"
                     :: "r"(dA), "l"(sA));
    }
    #pragma unroll
    for (int j = 0; j < 8; j++) {                   // B rows 0..127 (pre-rounded W')
        int idx = tid + j * 128;
        int r = idx >> 3, c = idx & 7;
        uint32_t dB = base + (uint32_t)(AS_F * 4 + r * (ROWF * 4) + c * 16);
        const float* sB = gB + (size_t)r * DIN + kc + c * 4;
        asm volatile("cp.async.cg.shared.global [%0], [%1], 16;"
                     :: "r"(dB), "l"(sB));
    }
}

#define MMA_TF32(D, A, B) \
    asm volatile("mma.sync.aligned.m16n8k8.row.col.f32.tf32.tf32.f32 " \
                 "{%0,%1,%2,%3}, {%4,%5,%6,%7}, {%8,%9}, {%0,%1,%2,%3};" \
                 : "+f"((D)[0]), "+f"((D)[1]), "+f"((D)[2]), "+f"((D)[3]) \
                 : "r"((A)[0]), "r"((A)[1]), "r"((A)[2]), "r"((A)[3]), \
                   "r"((B)[0]), "r"((B)[1]))

// Load one kk-step's fragments into buffer `buf` (plain LDS, no cvt).
#define LOAD_FRAGS(As, Bs, kk, buf) do {                                     \
    const int cb_ = (kk) * 8 + tig;                                          \
    _Pragma("unroll")                                                        \
    for (int mi = 0; mi < 4; mi++) {                                         \
        const int r0_ = wm * 64 + mi * 16 + g;                               \
        a[buf][mi][0] = __float_as_uint((As)[r0_ * ROWF + cb_]);             \
        a[buf][mi][1] = __float_as_uint((As)[(r0_ + 8) * ROWF + cb_]);       \
        a[buf][mi][2] = __float_as_uint((As)[r0_ * ROWF + cb_ + 4]);         \
        a[buf][mi][3] = __float_as_uint((As)[(r0_ + 8) * ROWF + cb_ + 4]);   \
    }                                                                        \
    _Pragma("unroll")                                                        \
    for (int ni = 0; ni < 8; ni++) {                                         \
        const int n_ = wn * 64 + ni * 8 + g;                                 \
        b[buf][ni][0] = __float_as_uint((Bs)[n_ * ROWF + cb_]);              \
        b[buf][ni][1] = __float_as_uint((Bs)[n_ * ROWF + cb_ + 4]);          \
    }                                                                        \
} while (0)

__global__ void __launch_bounds__(128, 2)
gemm_tf32(const float* __restrict__ bias, float* __restrict__ out) {
    extern __shared__ float smf[];
    const uint32_t sb = smem_u32(smf);
    const int tid = threadIdx.x, lane = tid & 31, warp = tid >> 5;
    const int g = lane >> 2, tig = lane & 3;
    const int wm = warp >> 1, wn = warp & 1;        // 2 x 2 warp grid
    const int m0 = blockIdx.y * BM, n0 = blockIdx.x * BN;

    const float* gA = g_Xr + (size_t)m0 * DIN;
    const float* gB = g_Wp + (size_t)n0 * DIN;

    issue_stage(gA, gB, 0, 0, sb, tid);
    asm volatile("cp.async.commit_group;" ::: "memory");
    issue_stage(gA, gB, BK, 1, sb, tid);
    asm volatile("cp.async.commit_group;" ::: "memory");

    float acc[4][8][4];                             // 64x64 warp tile
    #pragma unroll
    for (int mi = 0; mi < 4; mi++)
        #pragma unroll
        for (int ni = 0; ni < 8; ni++)
            #pragma unroll
            for (int q = 0; q < 4; q++) acc[mi][ni][q] = 0.f;

    uint32_t a[2][4][4], b[2][8][2];                // double-buffered fragments

    const int NCH = DIN / BK;                       // 128 K-chunks
    for (int c = 0; c < NCH; c++) {
        asm volatile("cp.async.wait_group 1;" ::: "memory");
        __syncthreads();

        const float* As = smf + (c % STG) * STAGE_F;
        const float* Bs = As + AS_F;

        // Critical-path first: kk=0 fragment LDS before the LDGSTS burst.
        LOAD_FRAGS(As, Bs, 0, 0);

        if (c + 2 < NCH) issue_stage(gA, gB, (c + 2) * BK, (c + 2) % STG, sb, tid);
        asm volatile("cp.async.commit_group;" ::: "memory");

        #pragma unroll
        for (int kk = 0; kk < 4; kk++) {
            const int cur = kk & 1;
            if (kk < 3) {                            // prefetch into idle buffer
                const int nxt = (kk + 1) & 1;
                LOAD_FRAGS(As, Bs, kk + 1, nxt);
            }
            #pragma unroll
            for (int mi = 0; mi < 4; mi++)
                #pragma unroll
                for (int ni = 0; ni < 8; ni++)
                    MMA_TF32(acc[mi][ni], a[cur][mi], b[cur][ni]);
        }
    }

    // Epilogue: direct STG.64 per (row, 2-col) pair + bias.
    #pragma unroll
    for (int mi = 0; mi < 4; mi++) {
        const int row = m0 + wm * 64 + mi * 16 + g;
        #pragma unroll
        for (int ni = 0; ni < 8; ni++) {
            const int col = n0 + wn * 64 + ni * 8 + 2 * tig;
            const float2 bv = *(const float2*)(bias + col);
            float2 o0, o1;
            o0.x = acc[mi][ni][0] + bv.x; o0.y = acc[mi][ni][1] + bv.y;
            o1.x = acc[mi][ni][2] + bv.x; o1.y = acc[mi][ni][3] + bv.y;
            *(float2*)(out + (size_t)row * DOUT + col) = o0;
            *(float2*)(out + (size_t)(row + 8) * DOUT + col) = o1;
        }
    }
}

// ============================ launch ============================

extern "C" void kernel_launch(void* const* d_in, const int* in_sizes, int n_in,
                              void* d_out, int out_size) {
    const float* x    = (const float*)d_in[0];  // [4, 2048, 4096]
    const float* hu   = (const float*)d_in[1];  // [4096, 8]
    const float* W    = (const float*)d_in[2];  // [4096, 4096]
    const float* bias = (const float*)d_in[3];  // [4096]
    float* out = (float*)d_out;                 // [4, 2048, 4096]
    (void)in_sizes; (void)n_in; (void)out_size;

    cudaFuncSetAttribute(p2_kernel, cudaFuncAttributeMaxDynamicSharedMemorySize, P2_SMEM);
    cudaFuncSetAttribute(gemm_tf32, cudaFuncAttributeMaxDynamicSharedMemorySize, GEMM_SMEM);

    p0_round<<<(MTOT * DIN) / (256 * 4), 256>>>(x);
    p1a_norm<<<8, 256>>>(hu);
    p1b_gram<<<36, 32>>>();
    p1c_buildT<<<1, 32>>>();
    p2_kernel<<<512, 256, P2_SMEM>>>(W);
    gemm_tf32<<<dim3(DOUT / BN, MTOT / BM), 128, GEMM_SMEM>>>(bias, out);
}

// round 15
// speedup vs baseline: 5.3892x; 1.0770x over previous
// HRALinear on GB300 (compute_103 non-'a' toolchain => NO tcgen05/TMA).
// Compact-WY Householder prep + Ampere-style tf32 mma.sync GEMM.
//
// R15: swizzled K-permute, second attempt (R7 failed on banks). ROWF=32
// (no pad) + Latin-square group swizzle: row r stores K-group kk at group
// position p=(kk+(r&3))&3, elements inside in order [0,4,1,5,2,6,3,7].
// Fragment load = 1 LDS.64 @ r*32 + p*8 + 2tig; bank start = 8*((kk+g)%4)
// tiles {0,8,16,24} across g -> conflict-free (no 4g pad term this time).
// 64 fewer LDS issues per warp-chunk. Swizzle baked into g_Xr/g_Wp at
// P0/P2 (depends only on row&3, kk) so cp.async copies verbatim.
// GEMM structure else = R14. Bit-identical math: rel_err must stay
// 2.935996e-4 (canary for layout bugs).

#include <cuda_runtime.h>
#include <cstdint>

#define DIN  4096
#define DOUT 4096
#define RNK  8
#define MTOT 8192   // 4 * 2048 rows of x

// ---- static device scratch (allocation-free) ----
__device__ float g_UT[RNK * DIN];            // normalized u^T [8][4096]
__device__ float g_G[64];                    // Gram matrix
__device__ float g_T[64];                    // WY T matrix
__device__ float g_Wp[(size_t)DOUT * DIN];   // W' (tf32-rounded, swizzled)
__device__ float g_Xr[(size_t)MTOT * DIN];   // x  (tf32-rounded, swizzled)

// ============================ helpers ============================

static __device__ __forceinline__ uint32_t smem_u32(const void* p) {
    uint32_t a;
    asm("{ .reg .u64 t; cvta.to.shared.u64 t, %1; cvt.u32.u64 %0, t; }"
        : "=r"(a) : "l"(p));
    return a;
}

static __device__ __forceinline__ float tf32rf(float f) {
    uint32_t u;
    asm("cvt.rna.tf32.f32 %0, %1;" : "=r"(u) : "f"(f));
    return __uint_as_float(u);
}

// ============================ P0: round x to tf32 + swizzle ============================
// Thread owns 4 consecutive floats (4-aligned): k low bits j = 4q + jj.
// Dest within 32-float chunk: p = (kk + (m&3))&3; pos = p*8 + 2*jj + q.

__global__ void __launch_bounds__(256)
p0_round(const float* __restrict__ x) {
    size_t i = ((size_t)blockIdx.x * 256 + threadIdx.x) * 4;
    float4 v = *(const float4*)(x + i);
    const int m  = (int)(i >> 12);
    const int k  = (int)(i & 4095);
    const int kk = (k >> 3) & 3;
    const int q  = (k >> 2) & 1;
    const int p  = (kk + (m & 3)) & 3;
    float* o = g_Xr + ((size_t)m << 12) + (k & ~31) + p * 8 + q;
    o[0] = tf32rf(v.x);
    o[2] = tf32rf(v.y);
    o[4] = tf32rf(v.z);
    o[6] = tf32rf(v.w);
}

// ============================ P1a: normalize u columns (8 blocks) ============================

__global__ void __launch_bounds__(256)
p1a_norm(const float* __restrict__ hu) {
    __shared__ float s_part[8];
    const int i = blockIdx.x;                 // column 0..7
    const int tid = threadIdx.x, wid = tid >> 5, lid = tid & 31;

    float s = 0.f;
    for (int k = tid; k < DIN; k += 256) {
        float v = hu[(size_t)k * RNK + i];
        s += v * v;
    }
    #pragma unroll
    for (int o = 16; o; o >>= 1) s += __shfl_xor_sync(0xFFFFFFFFu, s, o);
    if (lid == 0) s_part[wid] = s;
    __syncthreads();
    if (tid == 0) {
        float t = 0.f;
        #pragma unroll
        for (int w = 0; w < 8; w++) t += s_part[w];
        s_part[0] = rsqrtf(t);
    }
    __syncthreads();
    const float rn = s_part[0];
    for (int k = tid; k < DIN; k += 256)
        g_UT[i * DIN + k] = hu[(size_t)k * RNK + i] * rn;
}

// ============================ P1b: Gram pairs (36 blocks, 1 warp) ============================

__global__ void __launch_bounds__(32)
p1b_gram() {
    const int p = blockIdx.x;                 // pair index 0..35
    int i = 0, rem = p;
    while (rem >= RNK - i) { rem -= RNK - i; i++; }
    const int jj = i + rem;
    const int lid = threadIdx.x;

    float s = 0.f;
    for (int k = lid * 4; k < DIN; k += 128) {
        float4 a4 = *(const float4*)(g_UT + i * DIN + k);
        float4 b4 = *(const float4*)(g_UT + jj * DIN + k);
        s += a4.x * b4.x + a4.y * b4.y + a4.z * b4.z + a4.w * b4.w;
    }
    #pragma unroll
    for (int o = 16; o; o >>= 1) s += __shfl_xor_sync(0xFFFFFFFFu, s, o);
    if (lid == 0) { g_G[i * 8 + jj] = s; g_G[jj * 8 + i] = s; }
}

// ============================ P1c: WY T matrix (1 thread) ============================

__global__ void p1c_buildT() {
    if (threadIdx.x != 0 || blockIdx.x != 0) return;
    float T[64];
    #pragma unroll
    for (int m = 0; m < 64; m++) T[m] = 0.f;
    T[0] = 2.f;
    for (int k = 1; k < 8; k++) {
        for (int i = 0; i < k; i++) {
            float s = 0.f;
            for (int m2 = i; m2 < k; m2++) s += T[i * 8 + m2] * g_G[m2 * 8 + k];
            T[i * 8 + k] = -2.f * s;
        }
        T[k * 8 + k] = 2.f;
    }
    for (int m = 0; m < 64; m++) g_T[m] = T[m];
}

// ============================ P2: W' = W - (W U) T U^T ============================

static constexpr int P2_SMEM = (RNK * DIN + 64) * 4;

__global__ void __launch_bounds__(256)
p2_kernel(const float* __restrict__ W) {
    extern __shared__ float s[];
    float* sUT = s;
    float* sT  = s + RNK * DIN;
    const int tid = threadIdx.x;

    for (int idx = tid * 4; idx < RNK * DIN; idx += 256 * 4)
        *(float4*)(sUT + idx) = *(const float4*)(g_UT + idx);
    if (tid < 64) sT[tid] = g_T[tid];
    __syncthreads();

    const int wid = tid >> 5, lid = tid & 31;
    const int j = blockIdx.x * 8 + wid;          // one W row per warp
    const float* wr = W + (size_t)j * DIN;
    const int rm = j & 3;

    float acc[8] = {0.f, 0.f, 0.f, 0.f, 0.f, 0.f, 0.f, 0.f};
    for (int k = lid * 4; k < DIN; k += 128) {
        float4 w4 = *(const float4*)(wr + k);
        #pragma unroll
        for (int i = 0; i < 8; i++) {
            float4 u4 = *(const float4*)(sUT + i * DIN + k);
            acc[i] += w4.x * u4.x + w4.y * u4.y + w4.z * u4.z + w4.w * u4.w;
        }
    }
    #pragma unroll
    for (int o = 16; o; o >>= 1) {
        #pragma unroll
        for (int i = 0; i < 8; i++)
            acc[i] += __shfl_xor_sync(0xFFFFFFFFu, acc[i], o);
    }
    float v[8];
    #pragma unroll
    for (int i = 0; i < 8; i++) {
        float sv = 0.f;
        #pragma unroll
        for (int m = 0; m < 8; m++) sv += acc[m] * sT[m * 8 + i];
        v[i] = sv;
    }

    float* wp = g_Wp + (size_t)j * DIN;
    for (int k = lid * 4; k < DIN; k += 128) {
        float4 w4 = *(const float4*)(wr + k);
        #pragma unroll
        for (int i = 0; i < 8; i++) {
            float4 u4 = *(const float4*)(sUT + i * DIN + k);
            w4.x -= v[i] * u4.x; w4.y -= v[i] * u4.y;
            w4.z -= v[i] * u4.z; w4.w -= v[i] * u4.w;
        }
        // tf32-RN round + swizzled scatter (same layout as P0)
        const int kk = (k >> 3) & 3;
        const int q  = (k >> 2) & 1;
        const int p  = (kk + rm) & 3;
        float* o = wp + (k & ~31) + p * 8 + q;
        o[0] = tf32rf(w4.x);
        o[2] = tf32rf(w4.y);
        o[4] = tf32rf(w4.z);
        o[6] = tf32rf(w4.w);
    }
}

// ============================ GEMM: out = Xr @ Wp^T + bias ============================

static constexpr int BM = 128, BN = 128, BK = 32, STG = 3;
static constexpr int ROWF    = 32;                  // NO pad (swizzle handles banks)
static constexpr int AS_F    = BM * ROWF;           // A stage: 4096 floats
static constexpr int BS_F    = BN * ROWF;           // B stage: 4096 floats
static constexpr int STAGE_F = AS_F + BS_F;         // 8192 floats = 32768 B
static constexpr int GEMM_SMEM = STG * STAGE_F * 4; // 98304 B (2 CTAs/SM)

// One stage: A 128x32 + B 128x32, 128 threads, 16 x 16B cp.async each.
// Identity copy: swizzle already baked into the global scratch rows.
static __device__ __forceinline__ void issue_stage(const float* gA, const float* gB,
                                                   int kc, int s, uint32_t sb, int tid) {
    uint32_t base = sb + (uint32_t)s * (STAGE_F * 4);
    #pragma unroll
    for (int j = 0; j < 8; j++) {                   // A rows 0..127
        int idx = tid + j * 128;
        int r = idx >> 3, c = idx & 7;
        uint32_t dA = base + (uint32_t)(r * (ROWF * 4) + c * 16);
        const float* sA = gA + (size_t)r * DIN + kc + c * 4;
        asm volatile("cp.async.cg.shared.global [%0], [%1], 16;"
                     :: "r"(dA), "l"(sA));
    }
    #pragma unroll
    for (int j = 0; j < 8; j++) {                   // B rows 0..127
        int idx = tid + j * 128;
        int r = idx >> 3, c = idx & 7;
        uint32_t dB = base + (uint32_t)(AS_F * 4 + r * (ROWF * 4) + c * 16);
        const float* sB = gB + (size_t)r * DIN + kc + c * 4;
        asm volatile("cp.async.cg.shared.global [%0], [%1], 16;"
                     :: "r"(dB), "l"(sB));
    }
}

#define MMA_TF32(D, A, B) \
    asm volatile("mma.sync.aligned.m16n8k8.row.col.f32.tf32.tf32.f32 " \
                 "{%0,%1,%2,%3}, {%4,%5,%6,%7}, {%8,%9}, {%0,%1,%2,%3};" \
                 : "+f"((D)[0]), "+f"((D)[1]), "+f"((D)[2]), "+f"((D)[3]) \
                 : "r"((A)[0]), "r"((A)[1]), "r"((A)[2]), "r"((A)[3]), \
                   "r"((B)[0]), "r"((B)[1]))

// Load one kk-step's fragments into buffer `buf`: all LDS.64.
// Group position p = (kk + (row&3)) & 3; row&3 == g&3 for all our rows.
#define LOAD_FRAGS(As, Bs, kk, buf) do {                                     \
    const int cb_ = (((kk) + rm4) & 3) * 8 + 2 * tig;                        \
    _Pragma("unroll")                                                        \
    for (int mi = 0; mi < 4; mi++) {                                         \
        const int r0_ = wm * 64 + mi * 16 + g;                               \
        float2 f0_ = *(const float2*)((As) + r0_ * ROWF + cb_);              \
        float2 f1_ = *(const float2*)((As) + (r0_ + 8) * ROWF + cb_);        \
        a[buf][mi][0] = __float_as_uint(f0_.x);                              \
        a[buf][mi][1] = __float_as_uint(f1_.x);                              \
        a[buf][mi][2] = __float_as_uint(f0_.y);                              \
        a[buf][mi][3] = __float_as_uint(f1_.y);                              \
    }                                                                        \
    _Pragma("unroll")                                                        \
    for (int ni = 0; ni < 8; ni++) {                                         \
        const int n_ = wn * 64 + ni * 8 + g;                                 \
        float2 fb_ = *(const float2*)((Bs) + n_ * ROWF + cb_);               \
        b[buf][ni][0] = __float_as_uint(fb_.x);                              \
        b[buf][ni][1] = __float_as_uint(fb_.y);                              \
    }                                                                        \
} while (0)

__global__ void __launch_bounds__(128, 2)
gemm_tf32(const float* __restrict__ bias, float* __restrict__ out) {
    extern __shared__ float smf[];
    const uint32_t sb = smem_u32(smf);
    const int tid = threadIdx.x, lane = tid & 31, warp = tid >> 5;
    const int g = lane >> 2, tig = lane & 3;
    const int rm4 = g & 3;
    const int wm = warp >> 1, wn = warp & 1;        // 2 x 2 warp grid
    const int m0 = blockIdx.y * BM, n0 = blockIdx.x * BN;

    const float* gA = g_Xr + (size_t)m0 * DIN;
    const float* gB = g_Wp + (size_t)n0 * DIN;

    issue_stage(gA, gB, 0, 0, sb, tid);
    asm volatile("cp.async.commit_group;" ::: "memory");
    issue_stage(gA, gB, BK, 1, sb, tid);
    asm volatile("cp.async.commit_group;" ::: "memory");

    float acc[4][8][4];                             // 64x64 warp tile
    #pragma unroll
    for (int mi = 0; mi < 4; mi++)
        #pragma unroll
        for (int ni = 0; ni < 8; ni++)
            #pragma unroll
            for (int q = 0; q < 4; q++) acc[mi][ni][q] = 0.f;

    uint32_t a[2][4][4], b[2][8][2];                // double-buffered fragments

    const int NCH = DIN / BK;                       // 128 K-chunks
    for (int c = 0; c < NCH; c++) {
        asm volatile("cp.async.wait_group 1;" ::: "memory");
        __syncthreads();

        const float* As = smf + (c % STG) * STAGE_F;
        const float* Bs = As + AS_F;

        // Critical-path first: kk=0 fragment LDS before the LDGSTS burst.
        LOAD_FRAGS(As, Bs, 0, 0);

        if (c + 2 < NCH) issue_stage(gA, gB, (c + 2) * BK, (c + 2) % STG, sb, tid);
        asm volatile("cp.async.commit_group;" ::: "memory");

        #pragma unroll
        for (int kk = 0; kk < 4; kk++) {
            const int cur = kk & 1;
            if (kk < 3) {                            // prefetch into idle buffer
                const int nxt = (kk + 1) & 1;
                LOAD_FRAGS(As, Bs, kk + 1, nxt);
            }
            #pragma unroll
            for (int mi = 0; mi < 4; mi++)
                #pragma unroll
                for (int ni = 0; ni < 8; ni++)
                    MMA_TF32(acc[mi][ni], a[cur][mi], b[cur][ni]);
        }
    }

    // Epilogue: direct STG.64 per (row, 2-col) pair + bias.
    #pragma unroll
    for (int mi = 0; mi < 4; mi++) {
        const int row = m0 + wm * 64 + mi * 16 + g;
        #pragma unroll
        for (int ni = 0; ni < 8; ni++) {
            const int col = n0 + wn * 64 + ni * 8 + 2 * tig;
            const float2 bv = *(const float2*)(bias + col);
            float2 o0, o1;
            o0.x = acc[mi][ni][0] + bv.x; o0.y = acc[mi][ni][1] + bv.y;
            o1.x = acc[mi][ni][2] + bv.x; o1.y = acc[mi][ni][3] + bv.y;
            *(float2*)(out + (size_t)row * DOUT + col) = o0;
            *(float2*)(out + (size_t)(row + 8) * DOUT + col) = o1;
        }
    }
}

// ============================ launch ============================

extern "C" void kernel_launch(void* const* d_in, const int* in_sizes, int n_in,
                              void* d_out, int out_size) {
    const float* x    = (const float*)d_in[0];  // [4, 2048, 4096]
    const float* hu   = (const float*)d_in[1];  // [4096, 8]
    const float* W    = (const float*)d_in[2];  // [4096, 4096]
    const float* bias = (const float*)d_in[3];  // [4096]
    float* out = (float*)d_out;                 // [4, 2048, 4096]
    (void)in_sizes; (void)n_in; (void)out_size;

    cudaFuncSetAttribute(p2_kernel, cudaFuncAttributeMaxDynamicSharedMemorySize, P2_SMEM);
    cudaFuncSetAttribute(gemm_tf32, cudaFuncAttributeMaxDynamicSharedMemorySize, GEMM_SMEM);

    p0_round<<<(MTOT * DIN) / (256 * 4), 256>>>(x);
    p1a_norm<<<8, 256>>>(hu);
    p1b_gram<<<36, 32>>>();
    p1c_buildT<<<1, 32>>>();
    p2_kernel<<<512, 256, P2_SMEM>>>(W);
    gemm_tf32<<<dim3(DOUT / BN, MTOT / BM), 128, GEMM_SMEM>>>(bias, out);
}